// round 14
// baseline (speedup 1.0000x reference)
#include <cuda_runtime.h>
#include <cuda_fp16.h>
#include <math.h>

#define D 64
#define NMAX 100000
#define EMAX 1600000

// Scratch (__device__ globals, allocation-free rule)
__device__ __half2 g_xwp[(size_t)NMAX * 64];   // (xw_low[c], xw_high[c]) per col
__device__ float   g_mlp[(size_t)NMAX * 64];   // relu(x@W_mlp)
__device__ __half2 g_acc[(size_t)NMAX * 64];   // SpMM accum, packed (low, high), fp16 atomics
__device__ __half2 g_B[(size_t)NMAX * 192];    // bucket sums, node-major: [node][k][64]
__device__ int4    g_rec[EMAX];                // {src|k<<20, dst, half2(vl,vh) bits, 0}

__device__ __forceinline__ void redh8(__half2* a, unsigned x, unsigned y, unsigned z, unsigned w) {
    asm volatile("red.global.add.noftz.v4.f16x2 [%0], {%1, %2, %3, %4};"
                 :: "l"(a), "r"(x), "r"(y), "r"(z), "r"(w) : "memory");
}

// Fused acc-zero + prep (streaming; block-range dispatch).
__global__ void __launch_bounds__(256) zp_kernel(const int* __restrict__ src,
                                                 const int* __restrict__ dst,
                                                 const int* __restrict__ lab,
                                                 const float* __restrict__ vl,
                                                 const float* __restrict__ vh,
                                                 int n, int e, int pb) {
    int b = blockIdx.x;
    if (b < pb) {
        int i = b * 256 + threadIdx.x;
        if (i >= e) return;
        int s = src[i], d = dst[i];
        int sl = lab[s], dl = lab[d];
        int k = ((sl | dl) < 0) ? 2 : ((sl != dl) ? 1 : 0);
        __half2 cv = __floats2half2_rn(vl[i], vh[i]);
        g_rec[i] = make_int4(s | (k << 20), d, *(int*)&cv, 0);
    } else {
        int j = (b - pb) * 256 + threadIdx.x;
        if (j < n * 16)
            ((float4*)g_acc)[j] = make_float4(0.f, 0.f, 0.f, 0.f);
    }
}

// Zero the bucket array (runs on side stream, overlapped with spmm).
__global__ void __launch_bounds__(256) zeroB_kernel(int n) {
    int j = blockIdx.x * blockDim.x + threadIdx.x;
    if (j < n * 48)
        ((float4*)g_B)[j] = make_float4(0.f, 0.f, 0.f, 0.f);
}

// 3 fused GEMMs: grid-stride over rows, weights loaded into shared ONCE per block.
__global__ void __launch_bounds__(256) gemm3_kernel(const float* __restrict__ x,
                                                    const float* __restrict__ wl,
                                                    const float* __restrict__ wh,
                                                    const float* __restrict__ wm,
                                                    int n) {
    __shared__ float sW[3][D][D];
    for (int i = threadIdx.x; i < D * D; i += blockDim.x) {
        sW[0][i >> 6][i & 63] = wl[i];
        sW[1][i >> 6][i & 63] = wh[i];
        sW[2][i >> 6][i & 63] = wm[i];
    }
    __syncthreads();
    int warp = threadIdx.x >> 5, lane = threadIdx.x & 31;
    int nwarps = (blockDim.x >> 5) * gridDim.x;
    for (int row = blockIdx.x * 8 + warp; row < n; row += nwarps) {
        float2 xv = *(const float2*)(x + (size_t)row * D + lane * 2);
        float a0 = 0.f, a1 = 0.f, b0 = 0.f, b1 = 0.f, c0 = 0.f, c1 = 0.f;
#pragma unroll
        for (int k = 0; k < D; k++) {
            float xk = __shfl_sync(0xffffffffu, (k & 1) ? xv.y : xv.x, k >> 1);
            a0 += xk * sW[0][k][lane];      a1 += xk * sW[0][k][lane + 32];
            b0 += xk * sW[1][k][lane];      b1 += xk * sW[1][k][lane + 32];
            c0 += xk * sW[2][k][lane];      c1 += xk * sW[2][k][lane + 32];
        }
        size_t o = (size_t)row * 64;
        g_xwp[o + lane]      = __floats2half2_rn(a0, b0);
        g_xwp[o + lane + 32] = __floats2half2_rn(a1, b1);
        g_mlp[o + lane] = fmaxf(c0, 0.f);
        g_mlp[o + lane + 32] = fmaxf(c1, 0.f);
    }
}

// pass1: edge-parallel SpMM. 16 threads/edge; record broadcast + ONE fp16x8 red.
__global__ void __launch_bounds__(256) spmm_kernel(int e) {
    int tid = blockIdx.x * blockDim.x + threadIdx.x;
    int eid = tid >> 4;
    if (eid >= e) return;
    int c4 = tid & 15;
    int4 rec = g_rec[eid];            // same 16B for all 16 lanes -> broadcast sector
    int s = rec.x & 0xFFFFF;
    __half2 cf = *(__half2*)&rec.z;
    float4 raw = ((const float4*)g_xwp)[(size_t)s * 16 + c4];
    __half2 p0 = __hmul2(*(__half2*)&raw.x, cf);
    __half2 p1 = __hmul2(*(__half2*)&raw.y, cf);
    __half2 p2 = __hmul2(*(__half2*)&raw.z, cf);
    __half2 p3 = __hmul2(*(__half2*)&raw.w, cf);
    redh8(g_acc + (size_t)rec.y * 64 + c4 * 4,
          *(unsigned*)&p0, *(unsigned*)&p1, *(unsigned*)&p2, *(unsigned*)&p3);
}

// pass2: bucketed aggregation; relu on the gather; node-major B. 16 threads/edge.
__global__ void __launch_bounds__(256) pass2_kernel(int e) {
    int tid = blockIdx.x * blockDim.x + threadIdx.x;
    int eid = tid >> 4;
    if (eid >= e) return;
    int c4 = tid & 15;
    int4 rec = g_rec[eid];
    int s = rec.x & 0xFFFFF;
    int k = rec.x >> 20;
    float4 raw = ((const float4*)g_acc)[(size_t)s * 16 + c4];
    __half2 z = __float2half2_rn(0.f);
    __half2 p0 = __hmax2(*(__half2*)&raw.x, z);
    __half2 p1 = __hmax2(*(__half2*)&raw.y, z);
    __half2 p2 = __hmax2(*(__half2*)&raw.z, z);
    __half2 p3 = __hmax2(*(__half2*)&raw.w, z);
    redh8(g_B + ((size_t)rec.y * 3 + k) * 64 + c4 * 4,
          *(unsigned*)&p0, *(unsigned*)&p1, *(unsigned*)&p2, *(unsigned*)&p3);
}

// nodeB: streamed epilogue. Lane-parallel scalar section: lane (l&7) owns slot j.
__global__ void __launch_bounds__(256) nodeB_kernel(
        const float* __restrict__ alf, const float* __restrict__ ahf,
        const float* __restrict__ alb, const float* __restrict__ ahb,
        const float* __restrict__ alu, const float* __restrict__ ahu,
        const float* __restrict__ am,  const float* __restrict__ a7,
        float* __restrict__ out, int n) {
    __shared__ float sV[7][D];   // slot order: alf,ahf,alb,ahb,alu,ahu,am
    __shared__ float sA7[49];
    if (threadIdx.x < D) {
        int c = threadIdx.x;
        sV[0][c] = alf[c]; sV[1][c] = ahf[c]; sV[2][c] = alb[c];
        sV[3][c] = ahb[c]; sV[4][c] = alu[c]; sV[5][c] = ahu[c];
        sV[6][c] = am[c];
    }
    if (threadIdx.x < 49) sA7[threadIdx.x] = a7[threadIdx.x];
    __syncthreads();
    int warp = threadIdx.x >> 5, lane = threadIdx.x & 31;
    int node = blockIdx.x * 8 + warp;
    if (node >= n) return;
    int c = lane * 2;
    size_t nb = (size_t)node * 192;   // node-major bucket base (half2 units)
    float2 homo2 = ((const float2*)(g_B + nb))[lane];
    float2 hete2 = ((const float2*)(g_B + nb + 64))[lane];
    float2 unk2  = ((const float2*)(g_B + nb + 128))[lane];
    float2 m2    = ((const float2*)(g_mlp + (size_t)node * 64))[lane];
    float2 hoA = __half22float2(((__half2*)&homo2)[0]);  // x=low[c], y=high[c]
    float2 hoB = __half22float2(((__half2*)&homo2)[1]);  // col c+1
    float2 heA = __half22float2(((__half2*)&hete2)[0]);
    float2 heB = __half22float2(((__half2*)&hete2)[1]);
    float2 unA = __half22float2(((__half2*)&unk2)[0]);
    float2 unB = __half22float2(((__half2*)&unk2)[1]);

    float ps[7];
    ps[0] = heA.x * sV[0][c] + heB.x * sV[0][c + 1];
    ps[1] = heA.y * sV[1][c] + heB.y * sV[1][c + 1];
    ps[2] = hoA.x * sV[2][c] + hoB.x * sV[2][c + 1];
    ps[3] = hoA.y * sV[3][c] + hoB.y * sV[3][c + 1];
    ps[4] = unA.x * sV[4][c] + unB.x * sV[4][c + 1];
    ps[5] = unA.y * sV[5][c] + unB.y * sV[5][c + 1];
    ps[6] = m2.x  * sV[6][c] + m2.y  * sV[6][c + 1];
#pragma unroll
    for (int off = 16; off; off >>= 1)
#pragma unroll
        for (int j = 0; j < 7; j++)
            ps[j] += __shfl_xor_sync(0xffffffffu, ps[j], off);

    // ---- lane-parallel scalar block: lane (l&7)==j owns slot j (groups of 8 replicate) ----
    int lj = lane & 7;
    float myps = ps[0];
    if (lj == 1) myps = ps[1];
    else if (lj == 2) myps = ps[2];
    else if (lj == 3) myps = ps[3];
    else if (lj == 4) myps = ps[4];
    else if (lj == 5) myps = ps[5];
    else if (lj == 6) myps = ps[6];
    float myf = 1.f / (1.f + __expf(-myps));     // ONE sigmoid per lane

    float fb[7];
#pragma unroll
    for (int j = 0; j < 7; j++)
        fb[j] = __shfl_sync(0xffffffffu, myf, j, 8);

    float lgv = 0.f;
    if (lj < 7) {
#pragma unroll
        for (int j = 0; j < 7; j++)
            lgv += fb[j] * sA7[j * 7 + lj];
        lgv *= (1.0f / 7.0f);
    } else {
        lgv = -1e30f;                            // excluded from max; exp -> 0
    }
    float mx = lgv;
#pragma unroll
    for (int off = 4; off; off >>= 1)
        mx = fmaxf(mx, __shfl_xor_sync(0xffffffffu, mx, off, 8));
    float ev = __expf(lgv - mx);                 // lane 7: exp(-huge)=0
    float sm = ev;
#pragma unroll
    for (int off = 4; off; off >>= 1)
        sm += __shfl_xor_sync(0xffffffffu, sm, off, 8);
    float w = ev * (7.0f / sm);                  // this lane's attention weight (slot lj)

    float lg[7];
#pragma unroll
    for (int i = 0; i < 7; i++)
        lg[i] = __shfl_sync(0xffffffffu, w, i, 8);

    float2 r;
    r.x = lg[0] * heA.x + lg[1] * heA.y + lg[2] * hoA.x + lg[3] * hoA.y
        + lg[4] * unA.x + lg[5] * unA.y + lg[6] * m2.x;
    r.y = lg[0] * heB.x + lg[1] * heB.y + lg[2] * hoB.x + lg[3] * hoB.y
        + lg[4] * unB.x + lg[5] * unB.y + lg[6] * m2.y;
    *(float2*)(out + (size_t)node * 64 + c) = r;
}

extern "C" void kernel_launch(void* const* d_in, const int* in_sizes, int n_in,
                              void* d_out, int out_size) {
    const float* x   = (const float*)d_in[0];
    const float* vl  = (const float*)d_in[1];
    const float* vh  = (const float*)d_in[2];
    const float* wl  = (const float*)d_in[3];
    const float* wh  = (const float*)d_in[4];
    const float* wm  = (const float*)d_in[5];
    const float* alf = (const float*)d_in[6];
    const float* ahf = (const float*)d_in[7];
    const float* alb = (const float*)d_in[8];
    const float* ahb = (const float*)d_in[9];
    const float* alu = (const float*)d_in[10];
    const float* ahu = (const float*)d_in[11];
    const float* am  = (const float*)d_in[12];
    const float* a7  = (const float*)d_in[13];
    const int* src   = (const int*)d_in[14];
    const int* dst   = (const int*)d_in[15];
    const int* lab   = (const int*)d_in[16];
    int n = in_sizes[0] / D;
    int e = in_sizes[14];
    float* out = (float*)d_out;

    cudaStream_t s2;
    cudaEvent_t evFork, evGemm, evBzero;
    cudaStreamCreateWithFlags(&s2, cudaStreamNonBlocking);
    cudaEventCreateWithFlags(&evFork, cudaEventDisableTiming);
    cudaEventCreateWithFlags(&evGemm, cudaEventDisableTiming);
    cudaEventCreateWithFlags(&evBzero, cudaEventDisableTiming);

    // s2: gemm3 -> zeroB (zeroB overlaps spmm on main)
    cudaEventRecord(evFork, 0);
    cudaStreamWaitEvent(s2, evFork, 0);
    gemm3_kernel<<<640, 256, 0, s2>>>(x, wl, wh, wm, n);
    cudaEventRecord(evGemm, s2);
    zeroB_kernel<<<(n * 48 + 255) / 256, 256, 0, s2>>>(n);
    cudaEventRecord(evBzero, s2);

    // main: prep + acc-zero, then spmm (needs xwp), then pass2 (needs B zeroed)
    int pb = (e + 255) / 256;                  // prep blocks
    int zb = (n * 16 + 255) / 256;             // acc-zero blocks
    zp_kernel<<<pb + zb, 256>>>(src, dst, lab, vl, vh, n, e, pb);

    cudaStreamWaitEvent(0, evGemm, 0);
    int et = e * 16;
    spmm_kernel<<<(et + 255) / 256, 256>>>(e);
    cudaStreamWaitEvent(0, evBzero, 0);
    pass2_kernel<<<(et + 255) / 256, 256>>>(e);
    nodeB_kernel<<<(n + 7) / 8, 256>>>(alf, ahf, alb, ahb, alu, ahu, am, a7, out, n);
}

// round 15
// speedup vs baseline: 1.5589x; 1.5589x over previous
#include <cuda_runtime.h>
#include <cuda_fp16.h>
#include <math.h>

#define D 64
#define NMAX 100000
#define EMAX 1600000

// Scratch (__device__ globals, allocation-free rule)
__device__ __half2 g_xwp[(size_t)NMAX * 64];   // (xw_low[c], xw_high[c]) per col
__device__ float   g_mlp[(size_t)NMAX * 64];   // relu(x@W_mlp)
__device__ __half2 g_acc[(size_t)NMAX * 64];   // SpMM accum, packed (low, high), fp16 atomics
__device__ __half2 g_B[(size_t)NMAX * 192];    // bucket sums, node-major: [node][k][64]
__device__ int4    g_rec[EMAX];                // {src|k<<20, dst, half2(vl,vh) bits, 0}

__device__ __forceinline__ void redh8(__half2* a, unsigned x, unsigned y, unsigned z, unsigned w) {
    asm volatile("red.global.add.noftz.v4.f16x2 [%0], {%1, %2, %3, %4};"
                 :: "l"(a), "r"(x), "r"(y), "r"(z), "r"(w) : "memory");
}

// Fused zero+prep (both smem-free streaming jobs; block-range dispatch).
__global__ void __launch_bounds__(256) zp_kernel(const int* __restrict__ src,
                                                 const int* __restrict__ dst,
                                                 const int* __restrict__ lab,
                                                 const float* __restrict__ vl,
                                                 const float* __restrict__ vh,
                                                 int n, int e, int pb) {
    int b = blockIdx.x;
    if (b < pb) {
        int i = b * 256 + threadIdx.x;
        if (i >= e) return;
        int s = src[i], d = dst[i];
        int sl = lab[s], dl = lab[d];
        int k = ((sl | dl) < 0) ? 2 : ((sl != dl) ? 1 : 0);
        __half2 cv = __floats2half2_rn(vl[i], vh[i]);
        g_rec[i] = make_int4(s | (k << 20), d, *(int*)&cv, 0);
    } else {
        int j = (b - pb) * 256 + threadIdx.x;
        int nacc = n * 16;                 // float4s in g_acc
        if (j < nacc) {
            ((float4*)g_acc)[j] = make_float4(0.f, 0.f, 0.f, 0.f);
        } else {
            int r = j - nacc;
            if (r < n * 48)
                ((float4*)g_B)[r] = make_float4(0.f, 0.f, 0.f, 0.f);
        }
    }
}

// 3 fused GEMMs: grid-stride over rows, weights loaded into shared ONCE per block.
__global__ void __launch_bounds__(256) gemm3_kernel(const float* __restrict__ x,
                                                    const float* __restrict__ wl,
                                                    const float* __restrict__ wh,
                                                    const float* __restrict__ wm,
                                                    int n) {
    __shared__ float sW[3][D][D];
    for (int i = threadIdx.x; i < D * D; i += blockDim.x) {
        sW[0][i >> 6][i & 63] = wl[i];
        sW[1][i >> 6][i & 63] = wh[i];
        sW[2][i >> 6][i & 63] = wm[i];
    }
    __syncthreads();
    int warp = threadIdx.x >> 5, lane = threadIdx.x & 31;
    int nwarps = (blockDim.x >> 5) * gridDim.x;
    for (int row = blockIdx.x * 8 + warp; row < n; row += nwarps) {
        float2 xv = *(const float2*)(x + (size_t)row * D + lane * 2);
        float a0 = 0.f, a1 = 0.f, b0 = 0.f, b1 = 0.f, c0 = 0.f, c1 = 0.f;
#pragma unroll
        for (int k = 0; k < D; k++) {
            float xk = __shfl_sync(0xffffffffu, (k & 1) ? xv.y : xv.x, k >> 1);
            a0 += xk * sW[0][k][lane];      a1 += xk * sW[0][k][lane + 32];
            b0 += xk * sW[1][k][lane];      b1 += xk * sW[1][k][lane + 32];
            c0 += xk * sW[2][k][lane];      c1 += xk * sW[2][k][lane + 32];
        }
        size_t o = (size_t)row * 64;
        g_xwp[o + lane]      = __floats2half2_rn(a0, b0);
        g_xwp[o + lane + 32] = __floats2half2_rn(a1, b1);
        g_mlp[o + lane] = fmaxf(c0, 0.f);
        g_mlp[o + lane + 32] = fmaxf(c1, 0.f);
    }
}

// pass1: edge-parallel SpMM. 16 threads/edge; record broadcast + ONE fp16x8 red.
__global__ void __launch_bounds__(256) spmm_kernel(int e) {
    int tid = blockIdx.x * blockDim.x + threadIdx.x;
    int eid = tid >> 4;
    if (eid >= e) return;
    int c4 = tid & 15;
    int4 rec = g_rec[eid];            // same 16B for all 16 lanes -> broadcast sector
    int s = rec.x & 0xFFFFF;
    __half2 cf = *(__half2*)&rec.z;
    float4 raw = ((const float4*)g_xwp)[(size_t)s * 16 + c4];
    __half2 p0 = __hmul2(*(__half2*)&raw.x, cf);
    __half2 p1 = __hmul2(*(__half2*)&raw.y, cf);
    __half2 p2 = __hmul2(*(__half2*)&raw.z, cf);
    __half2 p3 = __hmul2(*(__half2*)&raw.w, cf);
    redh8(g_acc + (size_t)rec.y * 64 + c4 * 4,
          *(unsigned*)&p0, *(unsigned*)&p1, *(unsigned*)&p2, *(unsigned*)&p3);
}

// pass2: bucketed aggregation; relu on the gather; node-major B. 16 threads/edge.
__global__ void __launch_bounds__(256) pass2_kernel(int e) {
    int tid = blockIdx.x * blockDim.x + threadIdx.x;
    int eid = tid >> 4;
    if (eid >= e) return;
    int c4 = tid & 15;
    int4 rec = g_rec[eid];
    int s = rec.x & 0xFFFFF;
    int k = rec.x >> 20;
    float4 raw = ((const float4*)g_acc)[(size_t)s * 16 + c4];
    __half2 z = __float2half2_rn(0.f);
    __half2 p0 = __hmax2(*(__half2*)&raw.x, z);
    __half2 p1 = __hmax2(*(__half2*)&raw.y, z);
    __half2 p2 = __hmax2(*(__half2*)&raw.z, z);
    __half2 p3 = __hmax2(*(__half2*)&raw.w, z);
    redh8(g_B + ((size_t)rec.y * 3 + k) * 64 + c4 * 4,
          *(unsigned*)&p0, *(unsigned*)&p1, *(unsigned*)&p2, *(unsigned*)&p3);
}

// nodeB: streamed epilogue. Lane-parallel scalar section: lane (l&7) owns slot j.
__global__ void __launch_bounds__(256) nodeB_kernel(
        const float* __restrict__ alf, const float* __restrict__ ahf,
        const float* __restrict__ alb, const float* __restrict__ ahb,
        const float* __restrict__ alu, const float* __restrict__ ahu,
        const float* __restrict__ am,  const float* __restrict__ a7,
        float* __restrict__ out, int n) {
    __shared__ float sV[7][D];   // slot order: alf,ahf,alb,ahb,alu,ahu,am
    __shared__ float sA7[49];
    if (threadIdx.x < D) {
        int c = threadIdx.x;
        sV[0][c] = alf[c]; sV[1][c] = ahf[c]; sV[2][c] = alb[c];
        sV[3][c] = ahb[c]; sV[4][c] = alu[c]; sV[5][c] = ahu[c];
        sV[6][c] = am[c];
    }
    if (threadIdx.x < 49) sA7[threadIdx.x] = a7[threadIdx.x];
    __syncthreads();
    int warp = threadIdx.x >> 5, lane = threadIdx.x & 31;
    int node = blockIdx.x * 8 + warp;
    if (node >= n) return;
    int c = lane * 2;
    size_t nb = (size_t)node * 192;   // node-major bucket base (half2 units)
    float2 homo2 = ((const float2*)(g_B + nb))[lane];
    float2 hete2 = ((const float2*)(g_B + nb + 64))[lane];
    float2 unk2  = ((const float2*)(g_B + nb + 128))[lane];
    float2 m2    = ((const float2*)(g_mlp + (size_t)node * 64))[lane];
    float2 hoA = __half22float2(((__half2*)&homo2)[0]);  // x=low[c], y=high[c]
    float2 hoB = __half22float2(((__half2*)&homo2)[1]);  // col c+1
    float2 heA = __half22float2(((__half2*)&hete2)[0]);
    float2 heB = __half22float2(((__half2*)&hete2)[1]);
    float2 unA = __half22float2(((__half2*)&unk2)[0]);
    float2 unB = __half22float2(((__half2*)&unk2)[1]);

    float ps[7];
    ps[0] = heA.x * sV[0][c] + heB.x * sV[0][c + 1];
    ps[1] = heA.y * sV[1][c] + heB.y * sV[1][c + 1];
    ps[2] = hoA.x * sV[2][c] + hoB.x * sV[2][c + 1];
    ps[3] = hoA.y * sV[3][c] + hoB.y * sV[3][c + 1];
    ps[4] = unA.x * sV[4][c] + unB.x * sV[4][c + 1];
    ps[5] = unA.y * sV[5][c] + unB.y * sV[5][c + 1];
    ps[6] = m2.x  * sV[6][c] + m2.y  * sV[6][c + 1];
#pragma unroll
    for (int off = 16; off; off >>= 1)
#pragma unroll
        for (int j = 0; j < 7; j++)
            ps[j] += __shfl_xor_sync(0xffffffffu, ps[j], off);

    // ---- lane-parallel scalar block: lane (l&7)==j owns slot j (groups of 8 replicate) ----
    int lj = lane & 7;
    float myps = ps[0];
    if (lj == 1) myps = ps[1];
    else if (lj == 2) myps = ps[2];
    else if (lj == 3) myps = ps[3];
    else if (lj == 4) myps = ps[4];
    else if (lj == 5) myps = ps[5];
    else if (lj == 6) myps = ps[6];
    float myf = 1.f / (1.f + __expf(-myps));     // ONE sigmoid per lane

    float fb[7];
#pragma unroll
    for (int j = 0; j < 7; j++)
        fb[j] = __shfl_sync(0xffffffffu, myf, j, 8);

    float lgv = 0.f;
    if (lj < 7) {
#pragma unroll
        for (int j = 0; j < 7; j++)
            lgv += fb[j] * sA7[j * 7 + lj];
        lgv *= (1.0f / 7.0f);
    } else {
        lgv = -1e30f;                            // excluded from max; exp -> 0
    }
    float mx = lgv;
#pragma unroll
    for (int off = 4; off; off >>= 1)
        mx = fmaxf(mx, __shfl_xor_sync(0xffffffffu, mx, off, 8));
    float ev = __expf(lgv - mx);                 // lane 7: exp(-huge)=0
    float sm = ev;
#pragma unroll
    for (int off = 4; off; off >>= 1)
        sm += __shfl_xor_sync(0xffffffffu, sm, off, 8);
    float w = ev * (7.0f / sm);                  // this lane's attention weight (slot lj)

    float lg[7];
#pragma unroll
    for (int i = 0; i < 7; i++)
        lg[i] = __shfl_sync(0xffffffffu, w, i, 8);

    float2 r;
    r.x = lg[0] * heA.x + lg[1] * heA.y + lg[2] * hoA.x + lg[3] * hoA.y
        + lg[4] * unA.x + lg[5] * unA.y + lg[6] * m2.x;
    r.y = lg[0] * heB.x + lg[1] * heB.y + lg[2] * hoB.x + lg[3] * hoB.y
        + lg[4] * unB.x + lg[5] * unB.y + lg[6] * m2.y;
    *(float2*)(out + (size_t)node * 64 + c) = r;
}

extern "C" void kernel_launch(void* const* d_in, const int* in_sizes, int n_in,
                              void* d_out, int out_size) {
    const float* x   = (const float*)d_in[0];
    const float* vl  = (const float*)d_in[1];
    const float* vh  = (const float*)d_in[2];
    const float* wl  = (const float*)d_in[3];
    const float* wh  = (const float*)d_in[4];
    const float* wm  = (const float*)d_in[5];
    const float* alf = (const float*)d_in[6];
    const float* ahf = (const float*)d_in[7];
    const float* alb = (const float*)d_in[8];
    const float* ahb = (const float*)d_in[9];
    const float* alu = (const float*)d_in[10];
    const float* ahu = (const float*)d_in[11];
    const float* am  = (const float*)d_in[12];
    const float* a7  = (const float*)d_in[13];
    const int* src   = (const int*)d_in[14];
    const int* dst   = (const int*)d_in[15];
    const int* lab   = (const int*)d_in[16];
    int n = in_sizes[0] / D;
    int e = in_sizes[14];
    float* out = (float*)d_out;

    // Fork: gemm3 on a side stream, zp on the main stream, join before spmm (R13 structure).
    cudaStream_t s2;
    cudaEvent_t evFork, evJoin;
    cudaStreamCreateWithFlags(&s2, cudaStreamNonBlocking);
    cudaEventCreateWithFlags(&evFork, cudaEventDisableTiming);
    cudaEventCreateWithFlags(&evJoin, cudaEventDisableTiming);

    cudaEventRecord(evFork, 0);
    cudaStreamWaitEvent(s2, evFork, 0);
    gemm3_kernel<<<640, 256, 0, s2>>>(x, wl, wh, wm, n);
    cudaEventRecord(evJoin, s2);

    int pb = (e + 255) / 256;              // prep blocks
    int zb = (n * 64 + 255) / 256;         // zero blocks (n*64 float4s)
    zp_kernel<<<pb + zb, 256>>>(src, dst, lab, vl, vh, n, e, pb);

    cudaStreamWaitEvent(0, evJoin, 0);
    int et = e * 16;
    spmm_kernel<<<(et + 255) / 256, 256>>>(e);
    pass2_kernel<<<(et + 255) / 256, 256>>>(e);
    nodeB_kernel<<<(n + 7) / 8, 256>>>(alf, ahf, alb, ahb, alu, ahu, am, a7, out, n);
}

// round 17
// speedup vs baseline: 1.7189x; 1.1026x over previous
#include <cuda_runtime.h>
#include <cuda_fp16.h>
#include <math.h>

#define D 64
#define NMAX 100000
#define EMAX 1600000

// Scratch (__device__ globals, allocation-free rule)
__device__ __half2 g_xwp[(size_t)NMAX * 64];   // (xw_low[c], xw_high[c]) per col
__device__ float   g_mlp[(size_t)NMAX * 64];   // relu(x@W_mlp)
__device__ __half2 g_acc[(size_t)NMAX * 64];   // SpMM accum, packed (low, high), fp16 atomics
__device__ __half2 g_B[(size_t)NMAX * 192];    // bucket sums, node-major: [node][k][64]
__device__ int4    g_rec[EMAX];                // {src|k<<20, dst, half2(vl,vh) bits, 0}

__device__ __forceinline__ void redh8(__half2* a, unsigned x, unsigned y, unsigned z, unsigned w) {
    asm volatile("red.global.add.noftz.v4.f16x2 [%0], {%1, %2, %3, %4};"
                 :: "l"(a), "r"(x), "r"(y), "r"(z), "r"(w) : "memory");
}

// Fused zero+prep (both smem-free streaming jobs; block-range dispatch).
__global__ void __launch_bounds__(256) zp_kernel(const int* __restrict__ src,
                                                 const int* __restrict__ dst,
                                                 const int* __restrict__ lab,
                                                 const float* __restrict__ vl,
                                                 const float* __restrict__ vh,
                                                 int n, int e, int pb) {
    int b = blockIdx.x;
    if (b < pb) {
        int i = b * 256 + threadIdx.x;
        if (i >= e) return;
        int s = src[i], d = dst[i];
        int sl = lab[s], dl = lab[d];
        int k = ((sl | dl) < 0) ? 2 : ((sl != dl) ? 1 : 0);
        __half2 cv = __floats2half2_rn(vl[i], vh[i]);
        g_rec[i] = make_int4(s | (k << 20), d, *(int*)&cv, 0);
    } else {
        int j = (b - pb) * 256 + threadIdx.x;
        int nacc = n * 16;                 // float4s in g_acc
        if (j < nacc) {
            ((float4*)g_acc)[j] = make_float4(0.f, 0.f, 0.f, 0.f);
        } else {
            int r = j - nacc;
            if (r < n * 48)
                ((float4*)g_B)[r] = make_float4(0.f, 0.f, 0.f, 0.f);
        }
    }
}

// 3 fused GEMMs: grid-stride over rows, weights loaded into shared ONCE per block.
__global__ void __launch_bounds__(256) gemm3_kernel(const float* __restrict__ x,
                                                    const float* __restrict__ wl,
                                                    const float* __restrict__ wh,
                                                    const float* __restrict__ wm,
                                                    int n) {
    __shared__ float sW[3][D][D];
    for (int i = threadIdx.x; i < D * D; i += blockDim.x) {
        sW[0][i >> 6][i & 63] = wl[i];
        sW[1][i >> 6][i & 63] = wh[i];
        sW[2][i >> 6][i & 63] = wm[i];
    }
    __syncthreads();
    int warp = threadIdx.x >> 5, lane = threadIdx.x & 31;
    int nwarps = (blockDim.x >> 5) * gridDim.x;
    for (int row = blockIdx.x * 8 + warp; row < n; row += nwarps) {
        float2 xv = *(const float2*)(x + (size_t)row * D + lane * 2);
        float a0 = 0.f, a1 = 0.f, b0 = 0.f, b1 = 0.f, c0 = 0.f, c1 = 0.f;
#pragma unroll
        for (int k = 0; k < D; k++) {
            float xk = __shfl_sync(0xffffffffu, (k & 1) ? xv.y : xv.x, k >> 1);
            a0 += xk * sW[0][k][lane];      a1 += xk * sW[0][k][lane + 32];
            b0 += xk * sW[1][k][lane];      b1 += xk * sW[1][k][lane + 32];
            c0 += xk * sW[2][k][lane];      c1 += xk * sW[2][k][lane + 32];
        }
        size_t o = (size_t)row * 64;
        g_xwp[o + lane]      = __floats2half2_rn(a0, b0);
        g_xwp[o + lane + 32] = __floats2half2_rn(a1, b1);
        g_mlp[o + lane] = fmaxf(c0, 0.f);
        g_mlp[o + lane + 32] = fmaxf(c1, 0.f);
    }
}

// pass1: edge-parallel SpMM. 16-lane group owns TWO edges -> 2 independent
// load->RED chains per lane (MLP 2).
__global__ void __launch_bounds__(256) spmm_kernel(int e) {
    int tid = blockIdx.x * blockDim.x + threadIdx.x;
    int g = tid >> 4;
    int e0 = g * 2;
    if (e0 >= e) return;
    int c4 = tid & 15;
    int4 r0 = g_rec[e0];
    int s0 = r0.x & 0xFFFFF;
    __half2 cf0 = *(__half2*)&r0.z;
    bool has1 = (e0 + 1) < e;
    int4 r1 = has1 ? g_rec[e0 + 1] : r0;
    int s1 = r1.x & 0xFFFFF;
    __half2 cf1 = *(__half2*)&r1.z;

    float4 raw0 = ((const float4*)g_xwp)[(size_t)s0 * 16 + c4];
    float4 raw1 = ((const float4*)g_xwp)[(size_t)s1 * 16 + c4];

    __half2 a0 = __hmul2(*(__half2*)&raw0.x, cf0);
    __half2 a1 = __hmul2(*(__half2*)&raw0.y, cf0);
    __half2 a2 = __hmul2(*(__half2*)&raw0.z, cf0);
    __half2 a3 = __hmul2(*(__half2*)&raw0.w, cf0);
    redh8(g_acc + (size_t)r0.y * 64 + c4 * 4,
          *(unsigned*)&a0, *(unsigned*)&a1, *(unsigned*)&a2, *(unsigned*)&a3);

    if (has1) {
        __half2 b0 = __hmul2(*(__half2*)&raw1.x, cf1);
        __half2 b1 = __hmul2(*(__half2*)&raw1.y, cf1);
        __half2 b2 = __hmul2(*(__half2*)&raw1.z, cf1);
        __half2 b3 = __hmul2(*(__half2*)&raw1.w, cf1);
        redh8(g_acc + (size_t)r1.y * 64 + c4 * 4,
              *(unsigned*)&b0, *(unsigned*)&b1, *(unsigned*)&b2, *(unsigned*)&b3);
    }
}

// pass2: bucketed aggregation; relu on the gather; node-major B.
// 16-lane group owns TWO edges (MLP 2).
__global__ void __launch_bounds__(256) pass2_kernel(int e) {
    int tid = blockIdx.x * blockDim.x + threadIdx.x;
    int g = tid >> 4;
    int e0 = g * 2;
    if (e0 >= e) return;
    int c4 = tid & 15;
    int4 r0 = g_rec[e0];
    int s0 = r0.x & 0xFFFFF;
    int k0 = r0.x >> 20;
    bool has1 = (e0 + 1) < e;
    int4 r1 = has1 ? g_rec[e0 + 1] : r0;
    int s1 = r1.x & 0xFFFFF;
    int k1 = r1.x >> 20;

    float4 raw0 = ((const float4*)g_acc)[(size_t)s0 * 16 + c4];
    float4 raw1 = ((const float4*)g_acc)[(size_t)s1 * 16 + c4];

    __half2 z = __float2half2_rn(0.f);
    __half2 a0 = __hmax2(*(__half2*)&raw0.x, z);
    __half2 a1 = __hmax2(*(__half2*)&raw0.y, z);
    __half2 a2 = __hmax2(*(__half2*)&raw0.z, z);
    __half2 a3 = __hmax2(*(__half2*)&raw0.w, z);
    redh8(g_B + ((size_t)r0.y * 3 + k0) * 64 + c4 * 4,
          *(unsigned*)&a0, *(unsigned*)&a1, *(unsigned*)&a2, *(unsigned*)&a3);

    if (has1) {
        __half2 b0 = __hmax2(*(__half2*)&raw1.x, z);
        __half2 b1 = __hmax2(*(__half2*)&raw1.y, z);
        __half2 b2 = __hmax2(*(__half2*)&raw1.z, z);
        __half2 b3 = __hmax2(*(__half2*)&raw1.w, z);
        redh8(g_B + ((size_t)r1.y * 3 + k1) * 64 + c4 * 4,
              *(unsigned*)&b0, *(unsigned*)&b1, *(unsigned*)&b2, *(unsigned*)&b3);
    }
}

// nodeB: streamed epilogue. Lane-parallel scalar section: lane (l&7) owns slot j.
__global__ void __launch_bounds__(256) nodeB_kernel(
        const float* __restrict__ alf, const float* __restrict__ ahf,
        const float* __restrict__ alb, const float* __restrict__ ahb,
        const float* __restrict__ alu, const float* __restrict__ ahu,
        const float* __restrict__ am,  const float* __restrict__ a7,
        float* __restrict__ out, int n) {
    __shared__ float sV[7][D];   // slot order: alf,ahf,alb,ahb,alu,ahu,am
    __shared__ float sA7[49];
    if (threadIdx.x < D) {
        int c = threadIdx.x;
        sV[0][c] = alf[c]; sV[1][c] = ahf[c]; sV[2][c] = alb[c];
        sV[3][c] = ahb[c]; sV[4][c] = alu[c]; sV[5][c] = ahu[c];
        sV[6][c] = am[c];
    }
    if (threadIdx.x < 49) sA7[threadIdx.x] = a7[threadIdx.x];
    __syncthreads();
    int warp = threadIdx.x >> 5, lane = threadIdx.x & 31;
    int node = blockIdx.x * 8 + warp;
    if (node >= n) return;
    int c = lane * 2;
    size_t nb = (size_t)node * 192;   // node-major bucket base (half2 units)
    float2 homo2 = ((const float2*)(g_B + nb))[lane];
    float2 hete2 = ((const float2*)(g_B + nb + 64))[lane];
    float2 unk2  = ((const float2*)(g_B + nb + 128))[lane];
    float2 m2    = ((const float2*)(g_mlp + (size_t)node * 64))[lane];
    float2 hoA = __half22float2(((__half2*)&homo2)[0]);  // x=low[c], y=high[c]
    float2 hoB = __half22float2(((__half2*)&homo2)[1]);  // col c+1
    float2 heA = __half22float2(((__half2*)&hete2)[0]);
    float2 heB = __half22float2(((__half2*)&hete2)[1]);
    float2 unA = __half22float2(((__half2*)&unk2)[0]);
    float2 unB = __half22float2(((__half2*)&unk2)[1]);

    float ps[7];
    ps[0] = heA.x * sV[0][c] + heB.x * sV[0][c + 1];
    ps[1] = heA.y * sV[1][c] + heB.y * sV[1][c + 1];
    ps[2] = hoA.x * sV[2][c] + hoB.x * sV[2][c + 1];
    ps[3] = hoA.y * sV[3][c] + hoB.y * sV[3][c + 1];
    ps[4] = unA.x * sV[4][c] + unB.x * sV[4][c + 1];
    ps[5] = unA.y * sV[5][c] + unB.y * sV[5][c + 1];
    ps[6] = m2.x  * sV[6][c] + m2.y  * sV[6][c + 1];
#pragma unroll
    for (int off = 16; off; off >>= 1)
#pragma unroll
        for (int j = 0; j < 7; j++)
            ps[j] += __shfl_xor_sync(0xffffffffu, ps[j], off);

    // ---- lane-parallel scalar block: lane (l&7)==j owns slot j ----
    int lj = lane & 7;
    float myps = ps[0];
    if (lj == 1) myps = ps[1];
    else if (lj == 2) myps = ps[2];
    else if (lj == 3) myps = ps[3];
    else if (lj == 4) myps = ps[4];
    else if (lj == 5) myps = ps[5];
    else if (lj == 6) myps = ps[6];
    float myf = 1.f / (1.f + __expf(-myps));     // ONE sigmoid per lane

    float fb[7];
#pragma unroll
    for (int j = 0; j < 7; j++)
        fb[j] = __shfl_sync(0xffffffffu, myf, j, 8);

    float lgv = 0.f;
    if (lj < 7) {
#pragma unroll
        for (int j = 0; j < 7; j++)
            lgv += fb[j] * sA7[j * 7 + lj];
        lgv *= (1.0f / 7.0f);
    } else {
        lgv = -1e30f;                            // excluded from max; exp -> 0
    }
    float mx = lgv;
#pragma unroll
    for (int off = 4; off; off >>= 1)
        mx = fmaxf(mx, __shfl_xor_sync(0xffffffffu, mx, off, 8));
    float ev = __expf(lgv - mx);                 // lane 7: exp(-huge)=0
    float sm = ev;
#pragma unroll
    for (int off = 4; off; off >>= 1)
        sm += __shfl_xor_sync(0xffffffffu, sm, off, 8);
    float w = ev * (7.0f / sm);                  // this lane's attention weight (slot lj)

    float lg[7];
#pragma unroll
    for (int i = 0; i < 7; i++)
        lg[i] = __shfl_sync(0xffffffffu, w, i, 8);

    float2 r;
    r.x = lg[0] * heA.x + lg[1] * heA.y + lg[2] * hoA.x + lg[3] * hoA.y
        + lg[4] * unA.x + lg[5] * unA.y + lg[6] * m2.x;
    r.y = lg[0] * heB.x + lg[1] * heB.y + lg[2] * hoB.x + lg[3] * hoB.y
        + lg[4] * unB.x + lg[5] * unB.y + lg[6] * m2.y;
    *(float2*)(out + (size_t)node * 64 + c) = r;
}

extern "C" void kernel_launch(void* const* d_in, const int* in_sizes, int n_in,
                              void* d_out, int out_size) {
    const float* x   = (const float*)d_in[0];
    const float* vl  = (const float*)d_in[1];
    const float* vh  = (const float*)d_in[2];
    const float* wl  = (const float*)d_in[3];
    const float* wh  = (const float*)d_in[4];
    const float* wm  = (const float*)d_in[5];
    const float* alf = (const float*)d_in[6];
    const float* ahf = (const float*)d_in[7];
    const float* alb = (const float*)d_in[8];
    const float* ahb = (const float*)d_in[9];
    const float* alu = (const float*)d_in[10];
    const float* ahu = (const float*)d_in[11];
    const float* am  = (const float*)d_in[12];
    const float* a7  = (const float*)d_in[13];
    const int* src   = (const int*)d_in[14];
    const int* dst   = (const int*)d_in[15];
    const int* lab   = (const int*)d_in[16];
    int n = in_sizes[0] / D;
    int e = in_sizes[14];
    float* out = (float*)d_out;

    // Fork: gemm3 on a side stream, zp on the main stream, join before spmm.
    cudaStream_t s2;
    cudaEvent_t evFork, evJoin;
    cudaStreamCreateWithFlags(&s2, cudaStreamNonBlocking);
    cudaEventCreateWithFlags(&evFork, cudaEventDisableTiming);
    cudaEventCreateWithFlags(&evJoin, cudaEventDisableTiming);

    cudaEventRecord(evFork, 0);
    cudaStreamWaitEvent(s2, evFork, 0);
    gemm3_kernel<<<640, 256, 0, s2>>>(x, wl, wh, wm, n);
    cudaEventRecord(evJoin, s2);

    int pb = (e + 255) / 256;              // prep blocks
    int zb = (n * 64 + 255) / 256;         // zero blocks (n*64 float4s)
    zp_kernel<<<pb + zb, 256>>>(src, dst, lab, vl, vh, n, e, pb);

    cudaStreamWaitEvent(0, evJoin, 0);
    int egroups = (e + 1) / 2;             // 16-lane groups, 2 edges each
    int et = egroups * 16;
    spmm_kernel<<<(et + 255) / 256, 256>>>(e);
    pass2_kernel<<<(et + 255) / 256, 256>>>(e);
    nodeB_kernel<<<(n + 7) / 8, 256>>>(alf, ahf, alb, ahb, alu, ahu, am, a7, out, n);
}